// round 12
// baseline (speedup 1.0000x reference)
#include <cuda_runtime.h>
#include <cstdint>

// Fixed shapes
#define BB   4
#define NN   4096
#define CC   128
#define DD   132      // 3 pts + 128 feats + slot131 = aa
#define NPT  1024

// Cluster config (fast path)
#define CPB  16       // CTAs per batch = cluster size (non-portable)
#define THR  256      // threads per CTA, 1 point per thread

// Fallback config (proven path)
#define FB_NBLK 32
#define FB_THR  128

// Statics
__device__ float g_Frow[BB][NN][DD];                   // point-major rows; [131]=aa
__device__ float g_aa[BB][NN];                         // norms (for fallback / fr side)
__device__ volatile float g_rval[BB][2][FB_NBLK];      // fallback sync slots
__device__ volatile int   g_ridx[BB][2][FB_NBLK];
__device__ volatile int   g_rtag[BB][2][FB_NBLK];

// ---------------------------------------------------------------------------
// PTX helpers
// ---------------------------------------------------------------------------
__device__ __forceinline__ uint32_t smem_u32(const void* p) {
    uint32_t a;
    asm("{ .reg .u64 t; cvta.to.shared.u64 t, %1; cvt.u32.u64 %0, t; }"
        : "=r"(a) : "l"(p));
    return a;
}
__device__ __forceinline__ void mbar_init(uint32_t a, uint32_t cnt) {
    asm volatile("mbarrier.init.shared.b64 [%0], %1;" :: "r"(a), "r"(cnt) : "memory");
}
__device__ __forceinline__ uint32_t mapa_u32(uint32_t a, uint32_t rank) {
    uint32_t r;
    asm("mapa.shared::cluster.u32 %0, %1, %2;" : "=r"(r) : "r"(a), "r"(rank));
    return r;
}
__device__ __forceinline__ void st_cluster_u64(uint32_t a, unsigned long long v) {
    asm volatile("st.shared::cluster.u64 [%0], %1;" :: "r"(a), "l"(v) : "memory");
}
__device__ __forceinline__ void mbar_arrive_cluster(uint32_t a) {
    asm volatile("mbarrier.arrive.release.cluster.shared::cluster.b64 _, [%0];" :: "r"(a) : "memory");
}
__device__ __forceinline__ void mbar_wait_par_acq_cluster(uint32_t a, uint32_t parity) {
    uint32_t done;
    do {
        asm volatile(
            "{\n\t.reg .pred p;\n\t"
            "mbarrier.try_wait.parity.acquire.cluster.shared::cta.b64 p, [%1], %2, 0x989680;\n\t"
            "selp.b32 %0, 1, 0, p;\n\t}"
            : "=r"(done) : "r"(a), "r"(parity) : "memory");
    } while (!done);
}
__device__ __forceinline__ void cluster_sync_all() {
    asm volatile("barrier.cluster.arrive.aligned;" ::: "memory");
    asm volatile("barrier.cluster.wait.aligned;" ::: "memory");
}

// ---------------------------------------------------------------------------
// Prep: aa in exact Grace/LLVM NEON reduce order (frozen), plus point-major
// row table (rows carry aa in slot 131).
// ---------------------------------------------------------------------------
__global__ void prep_kernel(const float* __restrict__ pts,
                            const float* __restrict__ feat)
{
    int t = blockIdx.x * blockDim.x + threadIdx.x;
    if (t >= BB * NN) return;
    int b = t / NN;
    int n = t % NN;

    float row[DD];
    row[0] = pts[((size_t)b * NN + n) * 3 + 0];
    row[1] = pts[((size_t)b * NN + n) * 3 + 1];
    row[2] = pts[((size_t)b * NN + n) * 3 + 2];

    const float* fb = feat + (size_t)b * CC * NN + n;
    #pragma unroll 4
    for (int c = 0; c < CC; c++) row[3 + c] = fb[(size_t)c * NN];

    // NEON-order reduce (VF=4 x IC=2, faddp horizontal, 3-elem scalar tail)
    float v0[4] = {0.f, 0.f, 0.f, 0.f};
    float v1[4] = {0.f, 0.f, 0.f, 0.f};
    #pragma unroll
    for (int i = 0; i < 16; i++) {
        #pragma unroll
        for (int j = 0; j < 4; j++) {
            float x0 = row[8 * i + j];
            v0[j] = __fmaf_rn(x0, x0, v0[j]);
            float x1 = row[8 * i + 4 + j];
            v1[j] = __fmaf_rn(x1, x1, v1[j]);
        }
    }
    float l0 = __fadd_rn(v0[0], v1[0]);
    float l1 = __fadd_rn(v0[1], v1[1]);
    float l2 = __fadd_rn(v0[2], v1[2]);
    float l3 = __fadd_rn(v0[3], v1[3]);
    float h  = __fadd_rn(__fadd_rn(l0, l1), __fadd_rn(l2, l3));
    h = __fmaf_rn(row[128], row[128], h);
    h = __fmaf_rn(row[129], row[129], h);
    h = __fmaf_rn(row[130], row[130], h);

    row[131] = h;          // aa rides in the row
    g_aa[b][n] = h;

    float* grow = &g_Frow[b][n][0];
    #pragma unroll 4
    for (int k = 0; k < DD; k++) grow[k] = row[k];
}

// ---------------------------------------------------------------------------
// FAST PATH: one 16-CTA cluster per batch; all-to-all DSMEM exchange.
// ---------------------------------------------------------------------------
__global__ void __launch_bounds__(THR, 1) __cluster_dims__(CPB, 1, 1)
fps_cluster_kernel(const float* __restrict__ pts,
                   const float* __restrict__ feat,
                   float* __restrict__ out)
{
    const int blk  = blockIdx.x;
    const int b    = blk / CPB;
    const int rank = blk % CPB;
    const int t    = threadIdx.x;
    const int lane = t & 31;
    const int w    = t >> 5;
    const int n    = rank * THR + t;     // global point id

    __shared__ __align__(8) unsigned long long s_bar;            // count = CPB
    __shared__ __align__(8) unsigned long long s_slots[2][CPB];  // all-to-all slots
    __shared__ __align__(16) float s_fl[DD];
    __shared__ float s_wv[THR / 32];
    __shared__ int   s_wi[THR / 32];

    const uint32_t bar_a = smem_u32((const void*)&s_bar);

    if (t == 0) mbar_init(bar_a, CPB);
    __syncthreads();
    cluster_sync_all();     // bars initialized before any remote arrive

    // My point's features in registers (identical bits, k = 0..130).
    float fr[131];
    {
        const float* pb = pts + ((size_t)b * NN + n) * 3;
        fr[0] = pb[0]; fr[1] = pb[1]; fr[2] = pb[2];
        const float* fb = feat + (size_t)b * CC * NN + n;
        #pragma unroll
        for (int c = 0; c < CC; c++) fr[3 + c] = fb[(size_t)c * NN];
    }
    const float aa_i = g_aa[b][n];

    float mind = 1e10f;
    int cur = 0;

    for (int s = 0; s < NPT; s++) {
        const int p = s & 1;
        if (rank == 0 && t == 0) out[b * NPT + s] = (float)cur;

        // Broadcast f_cur row (33 float4 from 5 cache lines; slot 131 = aa_cur).
        if (t < 33) ((float4*)s_fl)[t] = ((const float4*)&g_Frow[b][cur][0])[t];
        __syncthreads();

        // Frozen numerics: sequential single-accumulator fp32 FMA dot.
        float ab = 0.0f;
        #pragma unroll
        for (int k = 0; k < 131; k++)
            ab = __fmaf_rn(fr[k], s_fl[k], ab);
        float d = __fadd_rn(__fadd_rn(aa_i, s_fl[131]), -__fmul_rn(2.0f, ab));
        mind = fminf(mind, d);

        // Intra-CTA argmax (ties -> smaller index).
        float v = mind; int idx = n;
        #pragma unroll
        for (int off = 16; off; off >>= 1) {
            float v2 = __shfl_down_sync(0xffffffffu, v, off);
            int   i2 = __shfl_down_sync(0xffffffffu, idx, off);
            if (v2 > v || (v2 == v && i2 < idx)) { v = v2; idx = i2; }
        }
        if (lane == 0) { s_wv[w] = v; s_wi[w] = idx; }
        __syncthreads();

        // t0: reduce 8 warp slots, then fan out to ALL 16 CTAs (incl. self).
        if (t == 0) {
            v = s_wv[0]; idx = s_wi[0];
            #pragma unroll
            for (int u = 1; u < THR / 32; u++)
                if (s_wv[u] > v || (s_wv[u] == v && s_wi[u] < idx)) { v = s_wv[u]; idx = s_wi[u]; }

            unsigned long long pack =
                ((unsigned long long)__float_as_uint(v) << 32) | (unsigned)idx;
            uint32_t slot_a = smem_u32((const void*)&s_slots[p][rank]);
            #pragma unroll
            for (int r = 0; r < CPB; r++)
                st_cluster_u64(mapa_u32(slot_a, r), pack);
            #pragma unroll
            for (int r = 0; r < CPB; r++)
                mbar_arrive_cluster(mapa_u32(bar_a, r));
        }

        // Everyone waits locally (16 arrivals), then reduces slots redundantly.
        mbar_wait_par_acq_cluster(bar_a, p);

        unsigned long long pk = s_slots[p][0];
        float bv = __uint_as_float((unsigned)(pk >> 32));
        int   bi = (int)(unsigned)(pk & 0xffffffffULL);
        #pragma unroll
        for (int r = 1; r < CPB; r++) {
            unsigned long long pr = s_slots[p][r];
            float rv = __uint_as_float((unsigned)(pr >> 32));
            int   ri = (int)(unsigned)(pr & 0xffffffffULL);
            if (rv > bv || (rv == bv && ri < bi)) { bv = rv; bi = ri; }
        }
        cur = bi;
    }

    cluster_sync_all();     // no CTA exits while remote ops may target it
}

// ---------------------------------------------------------------------------
// FALLBACK: proven global-sync kernel (round-10 lineage).
// ---------------------------------------------------------------------------
__global__ void __launch_bounds__(FB_THR) fps_fallback_kernel(
    const float* __restrict__ pts,
    const float* __restrict__ feat,
    float* __restrict__ out)
{
    const int blk  = blockIdx.x;
    const int b    = blk >> 5;
    const int bk   = blk & 31;
    const int t    = threadIdx.x;
    const int lane = t & 31;
    const int w    = t >> 5;
    const int n    = bk * FB_THR + t;

    if (t == 0) { g_rtag[b][0][bk] = 0; g_rtag[b][1][bk] = 0; }
    __threadfence();

    float fr[131];
    {
        const float* pb = pts + ((size_t)b * NN + n) * 3;
        fr[0] = pb[0]; fr[1] = pb[1]; fr[2] = pb[2];
        const float* fb = feat + (size_t)b * CC * NN + n;
        #pragma unroll
        for (int c = 0; c < CC; c++) fr[3 + c] = fb[(size_t)c * NN];
    }

    __shared__ __align__(16) float s_fl[DD];
    __shared__ float s_wv[4];
    __shared__ int   s_wi[4];
    __shared__ int   s_cur;

    const float aa_i = g_aa[b][n];

    float mind = 1e10f;
    int cur = 0;

    for (int s = 0; s < NPT; s++) {
        const int p = s & 1;
        if (bk == 0 && t == 0) out[b * NPT + s] = (float)cur;

        if (t < 33) ((float4*)s_fl)[t] = ((const float4*)&g_Frow[b][cur][0])[t];
        __syncthreads();

        float ab = 0.0f;
        #pragma unroll
        for (int k = 0; k < 131; k++)
            ab = __fmaf_rn(fr[k], s_fl[k], ab);
        float d = __fadd_rn(__fadd_rn(aa_i, s_fl[131]), -__fmul_rn(2.0f, ab));
        mind = fminf(mind, d);

        float v = mind; int idx = n;
        #pragma unroll
        for (int off = 16; off; off >>= 1) {
            float v2 = __shfl_down_sync(0xffffffffu, v, off);
            int   i2 = __shfl_down_sync(0xffffffffu, idx, off);
            if (v2 > v || (v2 == v && i2 < idx)) { v = v2; idx = i2; }
        }
        if (lane == 0) { s_wv[w] = v; s_wi[w] = idx; }
        __syncthreads();

        if (t == 0) {
            for (int u = 1; u < 4; u++)
                if (s_wv[u] > v || (s_wv[u] == v && s_wi[u] < idx)) { v = s_wv[u]; idx = s_wi[u]; }
            g_rval[b][p][bk] = v;
            g_ridx[b][p][bk] = idx;
            __threadfence();
            g_rtag[b][p][bk] = s + 1;
        }

        if (w == 0) {
            while (g_rtag[b][p][lane] != s + 1) { }
            __threadfence();
            float pv = g_rval[b][p][lane];
            int   pi = g_ridx[b][p][lane];
            #pragma unroll
            for (int off = 16; off; off >>= 1) {
                float v2 = __shfl_down_sync(0xffffffffu, pv, off);
                int   i2 = __shfl_down_sync(0xffffffffu, pi, off);
                if (v2 > pv || (v2 == pv && i2 < pi)) { pv = v2; pi = i2; }
            }
            if (lane == 0) s_cur = pi;
        }
        __syncthreads();
        cur = s_cur;
    }
}

// ---------------------------------------------------------------------------
extern "C" void kernel_launch(void* const* d_in, const int* in_sizes, int n_in,
                              void* d_out, int out_size)
{
    const float* points   = nullptr;
    const float* features = nullptr;
    for (int i = 0; i < n_in; i++) {
        long long sz = in_sizes[i];
        if (sz == (long long)BB * NN * 3)       points   = (const float*)d_in[i];
        else if (sz == (long long)BB * CC * NN) features = (const float*)d_in[i];
    }
    if (!points)   points   = (const float*)d_in[0];
    if (!features) features = (const float*)d_in[1];

    float* out = (float*)d_out;
    (void)out_size;

    prep_kernel<<<(BB * NN + 255) / 256, 256>>>(points, features);

    bool cluster_ok = false;
    {
        cudaError_t e = cudaFuncSetAttribute(
            (const void*)fps_cluster_kernel,
            cudaFuncAttributeNonPortableClusterSizeAllowed, 1);
        if (e == cudaSuccess) {
            cudaLaunchConfig_t cfg = {};
            cfg.gridDim  = dim3(BB * CPB, 1, 1);
            cfg.blockDim = dim3(THR, 1, 1);
            cudaLaunchAttribute attrs[1];
            attrs[0].id = cudaLaunchAttributeClusterDimension;
            attrs[0].val.clusterDim = {CPB, 1, 1};
            cfg.attrs = attrs;
            cfg.numAttrs = 1;
            int num = 0;
            cudaError_t e2 = cudaOccupancyMaxActiveClusters(
                &num, (const void*)fps_cluster_kernel, &cfg);
            cluster_ok = (e2 == cudaSuccess && num >= 1);
        }
        (void)cudaGetLastError();
    }

    if (cluster_ok) {
        fps_cluster_kernel<<<BB * CPB, THR>>>(points, features, out);
    } else {
        fps_fallback_kernel<<<BB * FB_NBLK, FB_THR>>>(points, features, out);
    }
}

// round 13
// speedup vs baseline: 2.7262x; 2.7262x over previous
#include <cuda_runtime.h>
#include <cstdint>

// Fixed shapes
#define BB   4
#define NN   4096
#define CC   128
#define DPAD 132        // 3 pts + 128 feats + 1 zero pad (pad term is exact no-op)
#define NPT  1024
#define TILE 64
#define KT   33         // 132 = 4 * 33, chunks preserve ascending-k order

// Statics: k-major features, norms, full dist matrix (268 MB)
__device__ float g_G[BB][DPAD][NN];
__device__ float g_aa[BB][NN];
__device__ float g_dist[(size_t)BB * NN * NN];

// ---------------------------------------------------------------------------
// Prep: k-major G + aa in exact Grace/LLVM NEON reduce order (frozen).
// ---------------------------------------------------------------------------
__global__ void prep_kernel(const float* __restrict__ pts,
                            const float* __restrict__ feat)
{
    int t = blockIdx.x * blockDim.x + threadIdx.x;
    if (t >= BB * NN) return;
    int b = t / NN;
    int n = t % NN;

    float row[DPAD];
    row[0] = pts[((size_t)b * NN + n) * 3 + 0];
    row[1] = pts[((size_t)b * NN + n) * 3 + 1];
    row[2] = pts[((size_t)b * NN + n) * 3 + 2];

    const float* fb = feat + (size_t)b * CC * NN + n;
    #pragma unroll 4
    for (int c = 0; c < CC; c++) row[3 + c] = fb[(size_t)c * NN];
    row[131] = 0.0f;

    // NEON-order reduce (VF=4 x IC=2, faddp horizontal, 3-elem scalar tail)
    float v0[4] = {0.f, 0.f, 0.f, 0.f};
    float v1[4] = {0.f, 0.f, 0.f, 0.f};
    #pragma unroll
    for (int i = 0; i < 16; i++) {
        #pragma unroll
        for (int j = 0; j < 4; j++) {
            float x0 = row[8 * i + j];
            v0[j] = __fmaf_rn(x0, x0, v0[j]);
            float x1 = row[8 * i + 4 + j];
            v1[j] = __fmaf_rn(x1, x1, v1[j]);
        }
    }
    float l0 = __fadd_rn(v0[0], v1[0]);
    float l1 = __fadd_rn(v0[1], v1[1]);
    float l2 = __fadd_rn(v0[2], v1[2]);
    float l3 = __fadd_rn(v0[3], v1[3]);
    float h  = __fadd_rn(__fadd_rn(l0, l1), __fadd_rn(l2, l3));
    h = __fmaf_rn(row[128], row[128], h);
    h = __fmaf_rn(row[129], row[129], h);
    h = __fmaf_rn(row[130], row[130], h);
    g_aa[b][n] = h;

    // k-major scatter (coalesced across threads for each k)
    #pragma unroll 4
    for (int k = 0; k < DPAD; k++) g_G[b][k][n] = row[k];
}

// ---------------------------------------------------------------------------
// GEMM: dist[b][i][j] with FROZEN numerics — each output is ONE fp32 fma
// accumulator over k = 0..131 strictly ascending (k=131 term is exactly 0:
// fma(0,0,acc) == acc), then d = fadd(fadd(aa_i, aa_j), -fmul(2, ab)).
// 64x64 tile, 256 threads, 4x4 microtile, K in 4 ascending chunks of 33.
// ---------------------------------------------------------------------------
__global__ void __launch_bounds__(256) gemm_kernel()
{
    __shared__ __align__(16) float As[KT][TILE];
    __shared__ __align__(16) float Bs[KT][TILE];

    const int b  = blockIdx.z;
    const int i0 = blockIdx.y * TILE;
    const int j0 = blockIdx.x * TILE;

    const int tx = threadIdx.x % 16;
    const int ty = threadIdx.x / 16;
    const int ri = ty * 4;
    const int rj = tx * 4;

    float acc[4][4];
    #pragma unroll
    for (int ii = 0; ii < 4; ii++)
        #pragma unroll
        for (int jj = 0; jj < 4; jj++)
            acc[ii][jj] = 0.0f;

    #pragma unroll 1
    for (int kb = 0; kb < DPAD; kb += KT) {
        __syncthreads();
        for (int idx = threadIdx.x; idx < KT * TILE; idx += 256) {
            int k = idx / TILE;
            int n = idx % TILE;
            As[k][n] = g_G[b][kb + k][i0 + n];
            Bs[k][n] = g_G[b][kb + k][j0 + n];
        }
        __syncthreads();

        #pragma unroll
        for (int k = 0; k < KT; k++) {
            float4 a  = *(const float4*)&As[k][ri];
            float4 bv = *(const float4*)&Bs[k][rj];
            acc[0][0] = __fmaf_rn(a.x, bv.x, acc[0][0]);
            acc[0][1] = __fmaf_rn(a.x, bv.y, acc[0][1]);
            acc[0][2] = __fmaf_rn(a.x, bv.z, acc[0][2]);
            acc[0][3] = __fmaf_rn(a.x, bv.w, acc[0][3]);
            acc[1][0] = __fmaf_rn(a.y, bv.x, acc[1][0]);
            acc[1][1] = __fmaf_rn(a.y, bv.y, acc[1][1]);
            acc[1][2] = __fmaf_rn(a.y, bv.z, acc[1][2]);
            acc[1][3] = __fmaf_rn(a.y, bv.w, acc[1][3]);
            acc[2][0] = __fmaf_rn(a.z, bv.x, acc[2][0]);
            acc[2][1] = __fmaf_rn(a.z, bv.y, acc[2][1]);
            acc[2][2] = __fmaf_rn(a.z, bv.z, acc[2][2]);
            acc[2][3] = __fmaf_rn(a.z, bv.w, acc[2][3]);
            acc[3][0] = __fmaf_rn(a.w, bv.x, acc[3][0]);
            acc[3][1] = __fmaf_rn(a.w, bv.y, acc[3][1]);
            acc[3][2] = __fmaf_rn(a.w, bv.z, acc[3][2]);
            acc[3][3] = __fmaf_rn(a.w, bv.w, acc[3][3]);
        }
    }

    float aai[4], aaj[4];
    #pragma unroll
    for (int ii = 0; ii < 4; ii++) aai[ii] = g_aa[b][i0 + ri + ii];
    #pragma unroll
    for (int jj = 0; jj < 4; jj++) aaj[jj] = g_aa[b][j0 + rj + jj];

    float* db = g_dist + ((size_t)b << 24);
    #pragma unroll
    for (int ii = 0; ii < 4; ii++) {
        float4 o;
        o.x = __fadd_rn(__fadd_rn(aai[ii], aaj[0]), -__fmul_rn(2.0f, acc[ii][0]));
        o.y = __fadd_rn(__fadd_rn(aai[ii], aaj[1]), -__fmul_rn(2.0f, acc[ii][1]));
        o.z = __fadd_rn(__fadd_rn(aai[ii], aaj[2]), -__fmul_rn(2.0f, acc[ii][2]));
        o.w = __fadd_rn(__fadd_rn(aai[ii], aaj[3]), -__fmul_rn(2.0f, acc[ii][3]));
        *(float4*)&db[(size_t)(i0 + ri + ii) * NN + (j0 + rj)] = o;
    }
}

// ---------------------------------------------------------------------------
// FPS: 1 CTA per batch, 1024 threads, 4 pts/thread; zero cross-CTA sync.
// Frozen semantics: mind = fminf(mind, row), argmax first-occurrence ties.
// ---------------------------------------------------------------------------
__global__ void __launch_bounds__(1024) fps_kernel(float* __restrict__ out)
{
    const int b    = blockIdx.x;
    const int t    = threadIdx.x;
    const int lane = t & 31;
    const int wid  = t >> 5;

    const float* db = g_dist + ((size_t)b << 24);
    float* outb = out + b * NPT;

    __shared__ float s_v[32];
    __shared__ int   s_i[32];
    __shared__ int   s_cur;

    float m0 = 1e10f, m1 = 1e10f, m2 = 1e10f, m3 = 1e10f;
    int cur = 0;

    for (int s = 0; s < NPT; s++) {
        if (t == 0) outb[s] = (float)cur;

        float4 d = *(const float4*)(db + ((size_t)cur << 12) + t * 4);
        m0 = fminf(m0, d.x);
        m1 = fminf(m1, d.y);
        m2 = fminf(m2, d.z);
        m3 = fminf(m3, d.w);

        // local argmax, first occurrence on ties
        float v = m0; int idx = t * 4;
        if (m1 > v) { v = m1; idx = t * 4 + 1; }
        if (m2 > v) { v = m2; idx = t * 4 + 2; }
        if (m3 > v) { v = m3; idx = t * 4 + 3; }

        #pragma unroll
        for (int off = 16; off; off >>= 1) {
            float v2 = __shfl_down_sync(0xffffffffu, v, off);
            int   i2 = __shfl_down_sync(0xffffffffu, idx, off);
            if (v2 > v || (v2 == v && i2 < idx)) { v = v2; idx = i2; }
        }
        if (lane == 0) { s_v[wid] = v; s_i[wid] = idx; }
        __syncthreads();

        if (wid == 0) {
            v = s_v[lane]; idx = s_i[lane];
            #pragma unroll
            for (int off = 16; off; off >>= 1) {
                float v2 = __shfl_down_sync(0xffffffffu, v, off);
                int   i2 = __shfl_down_sync(0xffffffffu, idx, off);
                if (v2 > v || (v2 == v && i2 < idx)) { v = v2; idx = i2; }
            }
            if (lane == 0) s_cur = idx;
        }
        __syncthreads();
        cur = s_cur;
    }
}

// ---------------------------------------------------------------------------
extern "C" void kernel_launch(void* const* d_in, const int* in_sizes, int n_in,
                              void* d_out, int out_size)
{
    const float* points   = nullptr;
    const float* features = nullptr;
    for (int i = 0; i < n_in; i++) {
        long long sz = in_sizes[i];
        if (sz == (long long)BB * NN * 3)       points   = (const float*)d_in[i];
        else if (sz == (long long)BB * CC * NN) features = (const float*)d_in[i];
    }
    if (!points)   points   = (const float*)d_in[0];
    if (!features) features = (const float*)d_in[1];

    float* out = (float*)d_out;
    (void)out_size;

    prep_kernel<<<(BB * NN + 255) / 256, 256>>>(points, features);

    dim3 grid(NN / TILE, NN / TILE, BB);   // (64, 64, 4)
    gemm_kernel<<<grid, 256>>>();

    fps_kernel<<<BB, 1024>>>(out);
}

// round 14
// speedup vs baseline: 3.1060x; 1.1393x over previous
#include <cuda_runtime.h>
#include <cstdint>
#include <cmath>

// Fixed shapes
#define BB   4
#define NN   4096
#define CC   128
#define DPAD 132        // 3 pts + 128 feats + 1 zero pad (pad term is exact no-op)
#define NPT  1024
#define TILE 64
#define KT   33         // 132 = 4 * 33, ascending-k chunks
#define NTRI 2080       // 64*65/2 lower-triangle blocks

// Statics: k-major features, norms, full dist matrix (268 MB)
__device__ float g_G[BB][DPAD][NN];
__device__ float g_aa[BB][NN];
__device__ float g_dist[(size_t)BB * NN * NN];

// ---------------------------------------------------------------------------
// Prep: k-major G + aa in exact Grace/LLVM NEON reduce order (frozen).
// ---------------------------------------------------------------------------
__global__ void prep_kernel(const float* __restrict__ pts,
                            const float* __restrict__ feat)
{
    int t = blockIdx.x * blockDim.x + threadIdx.x;
    if (t >= BB * NN) return;
    int b = t / NN;
    int n = t % NN;

    float row[DPAD];
    row[0] = pts[((size_t)b * NN + n) * 3 + 0];
    row[1] = pts[((size_t)b * NN + n) * 3 + 1];
    row[2] = pts[((size_t)b * NN + n) * 3 + 2];

    const float* fb = feat + (size_t)b * CC * NN + n;
    #pragma unroll 4
    for (int c = 0; c < CC; c++) row[3 + c] = fb[(size_t)c * NN];
    row[131] = 0.0f;

    // NEON-order reduce (VF=4 x IC=2, faddp horizontal, 3-elem scalar tail)
    float v0[4] = {0.f, 0.f, 0.f, 0.f};
    float v1[4] = {0.f, 0.f, 0.f, 0.f};
    #pragma unroll
    for (int i = 0; i < 16; i++) {
        #pragma unroll
        for (int j = 0; j < 4; j++) {
            float x0 = row[8 * i + j];
            v0[j] = __fmaf_rn(x0, x0, v0[j]);
            float x1 = row[8 * i + 4 + j];
            v1[j] = __fmaf_rn(x1, x1, v1[j]);
        }
    }
    float l0 = __fadd_rn(v0[0], v1[0]);
    float l1 = __fadd_rn(v0[1], v1[1]);
    float l2 = __fadd_rn(v0[2], v1[2]);
    float l3 = __fadd_rn(v0[3], v1[3]);
    float h  = __fadd_rn(__fadd_rn(l0, l1), __fadd_rn(l2, l3));
    h = __fmaf_rn(row[128], row[128], h);
    h = __fmaf_rn(row[129], row[129], h);
    h = __fmaf_rn(row[130], row[130], h);
    g_aa[b][n] = h;

    #pragma unroll 4
    for (int k = 0; k < DPAD; k++) g_G[b][k][n] = row[k];
}

// ---------------------------------------------------------------------------
// GEMM (symmetric-half): lower-triangle 64x64 blocks only; off-diagonal
// blocks are mirrored through a padded smem transpose (bit-exact: the fma
// chain is identical under operand swap; fadd(aa_i,aa_j) is commutative).
// Frozen numerics: single fp32 fma accumulator, k ascending, then
// d = fadd(fadd(aa_i, aa_j), -fmul(2, ab)).
// ---------------------------------------------------------------------------
__global__ void __launch_bounds__(256) gemm_kernel()
{
    __shared__ __align__(16) float As[KT][TILE];
    __shared__ __align__(16) float Bs[KT][TILE];
    __shared__ float Ts[TILE][TILE + 1];      // transpose staging (padded)

    // Map linear block id -> lower-triangle (bi, bj), bj <= bi.
    int l  = blockIdx.x;
    int bi = (int)((sqrtf(8.0f * (float)l + 1.0f) - 1.0f) * 0.5f);
    while ((bi + 1) * (bi + 2) / 2 <= l) bi++;
    while (bi * (bi + 1) / 2 > l)        bi--;
    int bj = l - bi * (bi + 1) / 2;

    const int b  = blockIdx.y;
    const int i0 = bi * TILE;
    const int j0 = bj * TILE;

    const int tx = threadIdx.x % 16;
    const int ty = threadIdx.x / 16;
    const int ri = ty * 4;
    const int rj = tx * 4;

    float acc[4][4];
    #pragma unroll
    for (int ii = 0; ii < 4; ii++)
        #pragma unroll
        for (int jj = 0; jj < 4; jj++)
            acc[ii][jj] = 0.0f;

    #pragma unroll 1
    for (int kb = 0; kb < DPAD; kb += KT) {
        __syncthreads();
        for (int idx = threadIdx.x; idx < KT * TILE; idx += 256) {
            int k = idx / TILE;
            int n = idx % TILE;
            As[k][n] = g_G[b][kb + k][i0 + n];
            Bs[k][n] = g_G[b][kb + k][j0 + n];
        }
        __syncthreads();

        #pragma unroll
        for (int k = 0; k < KT; k++) {
            float4 a  = *(const float4*)&As[k][ri];
            float4 bv = *(const float4*)&Bs[k][rj];
            acc[0][0] = __fmaf_rn(a.x, bv.x, acc[0][0]);
            acc[0][1] = __fmaf_rn(a.x, bv.y, acc[0][1]);
            acc[0][2] = __fmaf_rn(a.x, bv.z, acc[0][2]);
            acc[0][3] = __fmaf_rn(a.x, bv.w, acc[0][3]);
            acc[1][0] = __fmaf_rn(a.y, bv.x, acc[1][0]);
            acc[1][1] = __fmaf_rn(a.y, bv.y, acc[1][1]);
            acc[1][2] = __fmaf_rn(a.y, bv.z, acc[1][2]);
            acc[1][3] = __fmaf_rn(a.y, bv.w, acc[1][3]);
            acc[2][0] = __fmaf_rn(a.z, bv.x, acc[2][0]);
            acc[2][1] = __fmaf_rn(a.z, bv.y, acc[2][1]);
            acc[2][2] = __fmaf_rn(a.z, bv.z, acc[2][2]);
            acc[2][3] = __fmaf_rn(a.z, bv.w, acc[2][3]);
            acc[3][0] = __fmaf_rn(a.w, bv.x, acc[3][0]);
            acc[3][1] = __fmaf_rn(a.w, bv.y, acc[3][1]);
            acc[3][2] = __fmaf_rn(a.w, bv.z, acc[3][2]);
            acc[3][3] = __fmaf_rn(a.w, bv.w, acc[3][3]);
        }
    }

    float aai[4], aaj[4];
    #pragma unroll
    for (int ii = 0; ii < 4; ii++) aai[ii] = g_aa[b][i0 + ri + ii];
    #pragma unroll
    for (int jj = 0; jj < 4; jj++) aaj[jj] = g_aa[b][j0 + rj + jj];

    // Final distances (frozen rounding sequence), kept for both writes.
    float dv[4][4];
    #pragma unroll
    for (int ii = 0; ii < 4; ii++)
        #pragma unroll
        for (int jj = 0; jj < 4; jj++)
            dv[ii][jj] = __fadd_rn(__fadd_rn(aai[ii], aaj[jj]),
                                   -__fmul_rn(2.0f, acc[ii][jj]));

    float* db = g_dist + ((size_t)b << 24);

    // Normal block (coalesced float4 rows).
    #pragma unroll
    for (int ii = 0; ii < 4; ii++) {
        float4 o = make_float4(dv[ii][0], dv[ii][1], dv[ii][2], dv[ii][3]);
        *(float4*)&db[(size_t)(i0 + ri + ii) * NN + (j0 + rj)] = o;
    }

    // Mirror block for off-diagonal: stage transposed, write coalesced.
    if (i0 != j0) {
        __syncthreads();
        #pragma unroll
        for (int ii = 0; ii < 4; ii++)
            #pragma unroll
            for (int jj = 0; jj < 4; jj++)
                Ts[rj + jj][ri + ii] = dv[ii][jj];
        __syncthreads();

        // 256 threads write 64x64: each thread 4 consecutive cols, 4 rows.
        int c = (threadIdx.x % 16) * 4;
        int r0 = threadIdx.x / 16;
        #pragma unroll
        for (int rr = 0; rr < 4; rr++) {
            int r = r0 + rr * 16;
            float4 o = make_float4(Ts[r][c], Ts[r][c + 1], Ts[r][c + 2], Ts[r][c + 3]);
            *(float4*)&db[(size_t)(j0 + r) * NN + (i0 + c)] = o;
        }
    }
}

// ---------------------------------------------------------------------------
// FPS: 1 CTA per batch, 1024 threads, 4 pts/thread; zero cross-CTA sync.
// ---------------------------------------------------------------------------
__global__ void __launch_bounds__(1024) fps_kernel(float* __restrict__ out)
{
    const int b    = blockIdx.x;
    const int t    = threadIdx.x;
    const int lane = t & 31;
    const int wid  = t >> 5;

    const float* db = g_dist + ((size_t)b << 24);
    float* outb = out + b * NPT;

    __shared__ float s_v[32];
    __shared__ int   s_i[32];
    __shared__ int   s_cur;

    float m0 = 1e10f, m1 = 1e10f, m2 = 1e10f, m3 = 1e10f;
    int cur = 0;

    for (int s = 0; s < NPT; s++) {
        if (t == 0) outb[s] = (float)cur;

        float4 d = *(const float4*)(db + ((size_t)cur << 12) + t * 4);
        m0 = fminf(m0, d.x);
        m1 = fminf(m1, d.y);
        m2 = fminf(m2, d.z);
        m3 = fminf(m3, d.w);

        float v = m0; int idx = t * 4;
        if (m1 > v) { v = m1; idx = t * 4 + 1; }
        if (m2 > v) { v = m2; idx = t * 4 + 2; }
        if (m3 > v) { v = m3; idx = t * 4 + 3; }

        #pragma unroll
        for (int off = 16; off; off >>= 1) {
            float v2 = __shfl_down_sync(0xffffffffu, v, off);
            int   i2 = __shfl_down_sync(0xffffffffu, idx, off);
            if (v2 > v || (v2 == v && i2 < idx)) { v = v2; idx = i2; }
        }
        if (lane == 0) { s_v[wid] = v; s_i[wid] = idx; }
        __syncthreads();

        if (wid == 0) {
            v = s_v[lane]; idx = s_i[lane];
            #pragma unroll
            for (int off = 16; off; off >>= 1) {
                float v2 = __shfl_down_sync(0xffffffffu, v, off);
                int   i2 = __shfl_down_sync(0xffffffffu, idx, off);
                if (v2 > v || (v2 == v && i2 < idx)) { v = v2; idx = i2; }
            }
            if (lane == 0) s_cur = idx;
        }
        __syncthreads();
        cur = s_cur;
    }
}

// ---------------------------------------------------------------------------
extern "C" void kernel_launch(void* const* d_in, const int* in_sizes, int n_in,
                              void* d_out, int out_size)
{
    const float* points   = nullptr;
    const float* features = nullptr;
    for (int i = 0; i < n_in; i++) {
        long long sz = in_sizes[i];
        if (sz == (long long)BB * NN * 3)       points   = (const float*)d_in[i];
        else if (sz == (long long)BB * CC * NN) features = (const float*)d_in[i];
    }
    if (!points)   points   = (const float*)d_in[0];
    if (!features) features = (const float*)d_in[1];

    float* out = (float*)d_out;
    (void)out_size;

    prep_kernel<<<(BB * NN + 255) / 256, 256>>>(points, features);

    dim3 grid(NTRI, BB);                  // 2080 lower-triangle blocks x 4 batches
    gemm_kernel<<<grid, 256>>>();

    fps_kernel<<<BB, 1024>>>(out);
}

// round 15
// speedup vs baseline: 3.1403x; 1.0110x over previous
#include <cuda_runtime.h>
#include <cstdint>
#include <cmath>

// Fixed shapes
#define BB   4
#define NN   4096
#define CC   128
#define DPAD 132        // 3 pts + 128 feats + 1 zero pad (exact no-op in the chain)
#define NPT  1024
#define TILE 128
#define KT   33         // 132 = 4 * 33, ascending-k chunks
#define NBT  32         // NN / TILE
#define NTRI (NBT * (NBT + 1) / 2)   // 528 lower-triangle blocks

// Statics: k-major features, norms, full dist matrix (268 MB)
__device__ float g_G[BB][DPAD][NN];
__device__ float g_aa[BB][NN];
__device__ float g_dist[(size_t)BB * NN * NN];

// ---------------------------------------------------------------------------
// Prep: k-major G + aa in exact Grace/LLVM NEON reduce order (frozen).
// ---------------------------------------------------------------------------
__global__ void prep_kernel(const float* __restrict__ pts,
                            const float* __restrict__ feat)
{
    int t = blockIdx.x * blockDim.x + threadIdx.x;
    if (t >= BB * NN) return;
    int b = t / NN;
    int n = t % NN;

    float row[DPAD];
    row[0] = pts[((size_t)b * NN + n) * 3 + 0];
    row[1] = pts[((size_t)b * NN + n) * 3 + 1];
    row[2] = pts[((size_t)b * NN + n) * 3 + 2];

    const float* fb = feat + (size_t)b * CC * NN + n;
    #pragma unroll 4
    for (int c = 0; c < CC; c++) row[3 + c] = fb[(size_t)c * NN];
    row[131] = 0.0f;

    float v0[4] = {0.f, 0.f, 0.f, 0.f};
    float v1[4] = {0.f, 0.f, 0.f, 0.f};
    #pragma unroll
    for (int i = 0; i < 16; i++) {
        #pragma unroll
        for (int j = 0; j < 4; j++) {
            float x0 = row[8 * i + j];
            v0[j] = __fmaf_rn(x0, x0, v0[j]);
            float x1 = row[8 * i + 4 + j];
            v1[j] = __fmaf_rn(x1, x1, v1[j]);
        }
    }
    float l0 = __fadd_rn(v0[0], v1[0]);
    float l1 = __fadd_rn(v0[1], v1[1]);
    float l2 = __fadd_rn(v0[2], v1[2]);
    float l3 = __fadd_rn(v0[3], v1[3]);
    float h  = __fadd_rn(__fadd_rn(l0, l1), __fadd_rn(l2, l3));
    h = __fmaf_rn(row[128], row[128], h);
    h = __fmaf_rn(row[129], row[129], h);
    h = __fmaf_rn(row[130], row[130], h);
    g_aa[b][n] = h;

    #pragma unroll 4
    for (int k = 0; k < DPAD; k++) g_G[b][k][n] = row[k];
}

// ---------------------------------------------------------------------------
// GEMM (symmetric-half, 128x128 tiles, 8x8 microtile, 256 threads).
// Frozen numerics: one fp32 fma accumulator per output, k strictly ascending;
// d = fadd(fadd(aa_i, aa_j), -fmul(2, ab)). Mirror is bit-exact (commutative
// fma multiplicands; commutative fadd). Mirror staged through retired As.
// ---------------------------------------------------------------------------
__global__ void __launch_bounds__(256, 2) gemm_kernel()
{
    __shared__ __align__(16) float As[KT][TILE];
    __shared__ __align__(16) float Bs[KT][TILE];

    // Linear id -> lower-triangle (bi, bj), bj <= bi, bi in 0..31.
    int l  = blockIdx.x;
    int bi = (int)((sqrtf(8.0f * (float)l + 1.0f) - 1.0f) * 0.5f);
    while ((bi + 1) * (bi + 2) / 2 <= l) bi++;
    while (bi * (bi + 1) / 2 > l)        bi--;
    int bj = l - bi * (bi + 1) / 2;

    const int b  = blockIdx.y;
    const int i0 = bi * TILE;
    const int j0 = bj * TILE;

    const int tx = threadIdx.x % 16;   // j direction, 8 cols each
    const int ty = threadIdx.x / 16;   // i direction, 8 rows each
    const int ri = ty * 8;
    const int rj = tx * 8;

    float acc[8][8];
    #pragma unroll
    for (int ii = 0; ii < 8; ii++)
        #pragma unroll
        for (int jj = 0; jj < 8; jj++)
            acc[ii][jj] = 0.0f;

    #pragma unroll 1
    for (int kb = 0; kb < DPAD; kb += KT) {
        __syncthreads();
        for (int idx = threadIdx.x; idx < KT * TILE; idx += 256) {
            int k = idx >> 7;          // /128
            int n = idx & 127;
            As[k][n] = g_G[b][kb + k][i0 + n];
            Bs[k][n] = g_G[b][kb + k][j0 + n];
        }
        __syncthreads();

        #pragma unroll 3
        for (int k = 0; k < KT; k++) {
            float4 a0 = *(const float4*)&As[k][ri];
            float4 a1 = *(const float4*)&As[k][ri + 4];
            float4 b0 = *(const float4*)&Bs[k][rj];
            float4 b1 = *(const float4*)&Bs[k][rj + 4];
            float av[8] = {a0.x, a0.y, a0.z, a0.w, a1.x, a1.y, a1.z, a1.w};
            float bv[8] = {b0.x, b0.y, b0.z, b0.w, b1.x, b1.y, b1.z, b1.w};
            #pragma unroll
            for (int ii = 0; ii < 8; ii++)
                #pragma unroll
                for (int jj = 0; jj < 8; jj++)
                    acc[ii][jj] = __fmaf_rn(av[ii], bv[jj], acc[ii][jj]);
        }
    }

    float aai[8], aaj[8];
    #pragma unroll
    for (int ii = 0; ii < 8; ii++) aai[ii] = g_aa[b][i0 + ri + ii];
    #pragma unroll
    for (int jj = 0; jj < 8; jj++) aaj[jj] = g_aa[b][j0 + rj + jj];

    // Final distances (frozen rounding), reused for both writes.
    float dv[8][8];
    #pragma unroll
    for (int ii = 0; ii < 8; ii++)
        #pragma unroll
        for (int jj = 0; jj < 8; jj++)
            dv[ii][jj] = __fadd_rn(__fadd_rn(aai[ii], aaj[jj]),
                                   -__fmul_rn(2.0f, acc[ii][jj]));

    float* db = g_dist + ((size_t)b << 24);

    // Normal block: 8 rows x 2 float4 per thread, coalesced.
    #pragma unroll
    for (int ii = 0; ii < 8; ii++) {
        float4 o0 = make_float4(dv[ii][0], dv[ii][1], dv[ii][2], dv[ii][3]);
        float4 o1 = make_float4(dv[ii][4], dv[ii][5], dv[ii][6], dv[ii][7]);
        size_t base = (size_t)(i0 + ri + ii) * NN + (j0 + rj);
        *(float4*)&db[base]     = o0;
        *(float4*)&db[base + 4] = o1;
    }

    // Mirror (off-diagonal): transpose in 32-col chunks via retired As buffer.
    if (i0 != j0) {
        float (*Ts)[129] = (float (*)[129])&As[0][0];   // 32 x 129 <= 33*128 floats
        #pragma unroll 1
        for (int c = 0; c < 4; c++) {
            __syncthreads();
            // Threads owning cols [32c, 32c+32): tx in [4c, 4c+4)
            if ((tx >> 2) == c) {
                int jb = rj - 32 * c;                    // 0..24
                #pragma unroll
                for (int jj = 0; jj < 8; jj++)
                    #pragma unroll
                    for (int ii = 0; ii < 8; ii++)
                        Ts[jb + jj][ri + ii] = dv[ii][jj];
            }
            __syncthreads();
            // Write 32 rows x 128 cols: 8 threads per row, 16 floats each.
            int r  = threadIdx.x >> 3;                   // 0..31
            int cc = (threadIdx.x & 7) * 16;             // 0,16,...,112
            size_t base = (size_t)(j0 + 32 * c + r) * NN + (i0 + cc);
            #pragma unroll
            for (int q = 0; q < 4; q++) {
                float4 o = make_float4(Ts[r][cc + 4*q], Ts[r][cc + 4*q + 1],
                                       Ts[r][cc + 4*q + 2], Ts[r][cc + 4*q + 3]);
                *(float4*)&db[base + 4*q] = o;
            }
        }
    }
}

// ---------------------------------------------------------------------------
// FPS: 1 CTA per batch, 1024 threads, 4 pts/thread; zero cross-CTA sync.
// ---------------------------------------------------------------------------
__global__ void __launch_bounds__(1024) fps_kernel(float* __restrict__ out)
{
    const int b    = blockIdx.x;
    const int t    = threadIdx.x;
    const int lane = t & 31;
    const int wid  = t >> 5;

    const float* db = g_dist + ((size_t)b << 24);
    float* outb = out + b * NPT;

    __shared__ float s_v[32];
    __shared__ int   s_i[32];
    __shared__ int   s_cur;

    float m0 = 1e10f, m1 = 1e10f, m2 = 1e10f, m3 = 1e10f;
    int cur = 0;

    for (int s = 0; s < NPT; s++) {
        if (t == 0) outb[s] = (float)cur;

        float4 d = *(const float4*)(db + ((size_t)cur << 12) + t * 4);
        m0 = fminf(m0, d.x);
        m1 = fminf(m1, d.y);
        m2 = fminf(m2, d.z);
        m3 = fminf(m3, d.w);

        float v = m0; int idx = t * 4;
        if (m1 > v) { v = m1; idx = t * 4 + 1; }
        if (m2 > v) { v = m2; idx = t * 4 + 2; }
        if (m3 > v) { v = m3; idx = t * 4 + 3; }

        #pragma unroll
        for (int off = 16; off; off >>= 1) {
            float v2 = __shfl_down_sync(0xffffffffu, v, off);
            int   i2 = __shfl_down_sync(0xffffffffu, idx, off);
            if (v2 > v || (v2 == v && i2 < idx)) { v = v2; idx = i2; }
        }
        if (lane == 0) { s_v[wid] = v; s_i[wid] = idx; }
        __syncthreads();

        if (wid == 0) {
            v = s_v[lane]; idx = s_i[lane];
            #pragma unroll
            for (int off = 16; off; off >>= 1) {
                float v2 = __shfl_down_sync(0xffffffffu, v, off);
                int   i2 = __shfl_down_sync(0xffffffffu, idx, off);
                if (v2 > v || (v2 == v && i2 < idx)) { v = v2; idx = i2; }
            }
            if (lane == 0) s_cur = idx;
        }
        __syncthreads();
        cur = s_cur;
    }
}

// ---------------------------------------------------------------------------
extern "C" void kernel_launch(void* const* d_in, const int* in_sizes, int n_in,
                              void* d_out, int out_size)
{
    const float* points   = nullptr;
    const float* features = nullptr;
    for (int i = 0; i < n_in; i++) {
        long long sz = in_sizes[i];
        if (sz == (long long)BB * NN * 3)       points   = (const float*)d_in[i];
        else if (sz == (long long)BB * CC * NN) features = (const float*)d_in[i];
    }
    if (!points)   points   = (const float*)d_in[0];
    if (!features) features = (const float*)d_in[1];

    float* out = (float*)d_out;
    (void)out_size;

    prep_kernel<<<(BB * NN + 255) / 256, 256>>>(points, features);

    dim3 grid(NTRI, BB);                  // 528 triangle blocks x 4 batches
    gemm_kernel<<<grid, 256>>>();

    fps_kernel<<<BB, 1024>>>(out);
}